// round 1
// baseline (speedup 1.0000x reference)
#include <cuda_runtime.h>

#define NN 24
#define IC 32
#define HC 32
#define THREADS 256
#define SPT 2                         // samples per thread
#define SPB (THREADS * SPT)           // samples per block = 512

// node -> flat weight index (g*4+k) and node -> group, from GROUPING
__constant__ int c_node2gk[NN] = {0,4,8,1,5,9,2,6,10,3,7,11,12,13,14,15,16,20,17,21,18,22,19,23};
__constant__ int c_node2g[NN]  = {0,1,2,0,1,2,0,1,2,0,1,2,3,3,3,3,4,5,4,5,4,5,4,5};
__constant__ int c_members[6*4] = {0,3,6,9, 1,4,7,10, 2,5,8,11, 12,13,14,15, 16,18,20,22, 17,19,21,23};

__device__ __forceinline__ unsigned long long pack2(float a, float b) {
    unsigned long long r;
    asm("mov.b64 %0, {%1, %2};" : "=l"(r) : "f"(a), "f"(b));
    return r;
}
__device__ __forceinline__ void unpack2(unsigned long long v, float &a, float &b) {
    asm("mov.b64 {%0, %1}, %2;" : "=f"(a), "=f"(b) : "l"(v));
}
__device__ __forceinline__ void ffma2(unsigned long long &d, unsigned long long a, unsigned long long b) {
    asm("fma.rn.f32x2 %0, %1, %2, %0;" : "+l"(d) : "l"(a), "l"(b));
}

__global__ __launch_bounds__(THREADS, 1)
void grouped_mlp_kernel(const float* __restrict__ h,
                        const int*   __restrict__ valid,
                        const float* __restrict__ W1,
                        const float* __restrict__ b1,
                        const float* __restrict__ W2,
                        const float* __restrict__ b2,
                        float* __restrict__ out)
{
    const int node = blockIdx.x;
    const int gk   = c_node2gk[node];
    const int g    = c_node2g[node];

    __shared__ __align__(16) float sW1[IC * HC];  // [l][j], j contiguous
    __shared__ __align__(16) float sW2[HC];
    __shared__ __align__(16) float sB1[HC];
    __shared__ float sB2;

    const int tid = threadIdx.x;
    {
        const float* w1p = W1 + gk * IC * HC;
        #pragma unroll
        for (int i = 0; i < (IC * HC) / THREADS; i++)
            sW1[tid + i * THREADS] = w1p[tid + i * THREADS];
        if (tid < HC) {
            sW2[tid] = W2[gk * HC + tid];
            sB1[tid] = b1[gk * HC + tid];
        }
        if (tid == 0) sB2 = b2[gk];
    }
    __syncthreads();

    const int s0 = blockIdx.y * SPB + tid;
    const int s1 = s0 + THREADS;

    // ---- load inputs (one full 128B line per sample-node row) + relu ----
    float xa[IC], xb[IC];
    {
        const float4* p0 = reinterpret_cast<const float4*>(h + ((size_t)s0 * NN + node) * IC);
        const float4* p1 = reinterpret_cast<const float4*>(h + ((size_t)s1 * NN + node) * IC);
        #pragma unroll
        for (int i = 0; i < 8; i++) {
            float4 v = p0[i];
            xa[4*i+0] = fmaxf(v.x, 0.f); xa[4*i+1] = fmaxf(v.y, 0.f);
            xa[4*i+2] = fmaxf(v.z, 0.f); xa[4*i+3] = fmaxf(v.w, 0.f);
        }
        #pragma unroll
        for (int i = 0; i < 8; i++) {
            float4 v = p1[i];
            xb[4*i+0] = fmaxf(v.x, 0.f); xb[4*i+1] = fmaxf(v.y, 0.f);
            xb[4*i+2] = fmaxf(v.z, 0.f); xb[4*i+3] = fmaxf(v.w, 0.f);
        }
    }

    // ---- group-valid masks ----
    float m0, m1;
    {
        const int* v0 = valid + (size_t)s0 * NN;
        const int* v1 = valid + (size_t)s1 * NN;
        int a = 0, b = 0;
        #pragma unroll
        for (int k = 0; k < 4; k++) {
            int mem = c_members[g * 4 + k];
            a += v0[mem];
            b += v1[mem];
        }
        m0 = (a > 0) ? 1.f : 0.f;
        m1 = (b > 0) ? 1.f : 0.f;
    }

    // ---- layer 1: hid[j] = b1[j] + sum_l x[l] * W1[l][j], f32x2 along j ----
    unsigned long long hid0[HC/2], hid1[HC/2];
    const unsigned long long* sW1u = reinterpret_cast<const unsigned long long*>(sW1);
    const unsigned long long* sB1u = reinterpret_cast<const unsigned long long*>(sB1);
    #pragma unroll
    for (int j2 = 0; j2 < HC/2; j2++) {
        unsigned long long bb = sB1u[j2];
        hid0[j2] = bb;
        hid1[j2] = bb;
    }

    #pragma unroll
    for (int l = 0; l < IC; l++) {
        unsigned long long x0 = pack2(xa[l], xa[l]);
        unsigned long long x1 = pack2(xb[l], xb[l]);
        #pragma unroll
        for (int j2 = 0; j2 < HC/2; j2++) {
            unsigned long long w = sW1u[l * (HC/2) + j2];   // LDS.64 broadcast
            ffma2(hid0[j2], x0, w);
            ffma2(hid1[j2], x1, w);
        }
    }

    // ---- layer 2: relu(hid) . W2 + b2 ----
    float acc0 = sB2, acc1 = sB2;
    #pragma unroll
    for (int j2 = 0; j2 < HC/2; j2++) {
        float a0, a1, c0, c1;
        unpack2(hid0[j2], a0, a1);
        unpack2(hid1[j2], c0, c1);
        float w0 = sW2[2*j2], w1v = sW2[2*j2+1];
        acc0 = fmaf(fmaxf(a0, 0.f), w0, acc0);
        acc0 = fmaf(fmaxf(a1, 0.f), w1v, acc0);
        acc1 = fmaf(fmaxf(c0, 0.f), w0, acc1);
        acc1 = fmaf(fmaxf(c1, 0.f), w1v, acc1);
    }

    out[(size_t)s0 * NN + node] = acc0 * m0;
    out[(size_t)s1 * NN + node] = acc1 * m1;
}

extern "C" void kernel_launch(void* const* d_in, const int* in_sizes, int n_in,
                              void* d_out, int out_size) {
    const float* h     = (const float*)d_in[0];
    const int*   valid = (const int*)  d_in[1];
    const float* W1    = (const float*)d_in[2];
    const float* b1    = (const float*)d_in[3];
    const float* W2    = (const float*)d_in[4];
    const float* b2    = (const float*)d_in[5];
    float* out = (float*)d_out;

    const int n_samples = in_sizes[0] / (NN * IC);   // 131072
    dim3 grid(NN, n_samples / SPB);                  // (24, 256)
    grouped_mlp_kernel<<<grid, THREADS>>>(h, valid, W1, b1, W2, b2, out);
}

// round 2
// speedup vs baseline: 1.1211x; 1.1211x over previous
#include <cuda_runtime.h>

#define NPB 4                     // nodes per block
#define TILE 128                  // samples per tile
#define THREADS 128
#define NSAMP 131072
#define NTILES (NSAMP / TILE)     // 1024
#define GRIDY 256                 // tiles strided -> 4 tiles per block
#define P 129                     // padded floats per l-row
#define NODE_STRIDE (32 * P + 1)  // 4129 floats per node block (skew +1)

typedef unsigned long long ull;

__constant__ int c_node2gk[24] = {0,4,8,1,5,9,2,6,10,3,7,11,12,13,14,15,16,20,17,21,18,22,19,23};
__constant__ int c_node2g[24]  = {0,1,2,0,1,2,0,1,2,0,1,2,3,3,3,3,4,5,4,5,4,5,4,5};
__constant__ int c_members[24] = {0,3,6,9, 1,4,7,10, 2,5,8,11, 12,13,14,15, 16,18,20,22, 17,19,21,23};

// smem float offsets
#define OFF_XBUF 0
#define OFF_W1   (OFF_XBUF + NPB * NODE_STRIDE)        // 16516
#define OFF_W2   (OFF_W1 + NPB * 1024)                 // 20612
#define OFF_B1   (OFF_W2 + NPB * 32)                   // 20740
#define OFF_B2   (OFF_B1 + NPB * 32)                   // 20868
#define OFF_GV   (OFF_B2 + 4)                          // 20872
#define OFF_OUT  (OFF_GV + 6 * TILE)                   // 21640
#define OFF_VAL  (OFF_OUT + TILE * 5)                  // 22280 (int area)
#define SMEM_FLOATS (OFF_VAL + TILE * 24)              // 25352
#define SMEM_BYTES (SMEM_FLOATS * 4)                   // 101408

__device__ __forceinline__ ull pack2(float a, float b) {
    ull r; asm("mov.b64 %0, {%1, %2};" : "=l"(r) : "f"(a), "f"(b)); return r;
}
__device__ __forceinline__ void unpack2(ull v, float &a, float &b) {
    asm("mov.b64 {%0, %1}, %2;" : "=f"(a), "=f"(b) : "l"(v));
}
__device__ __forceinline__ void ffma2(ull &d, ull a, ull b) {
    asm("fma.rn.f32x2 %0, %1, %2, %0;" : "+l"(d) : "l"(a), "l"(b));
}

__global__ __launch_bounds__(THREADS)
void grouped_mlp_kernel(const float4* __restrict__ h4,
                        const int4*   __restrict__ valid4,
                        const float4* __restrict__ W1_4,
                        const float*  __restrict__ b1,
                        const float*  __restrict__ W2,
                        const float*  __restrict__ b2,
                        float* __restrict__ out)
{
    extern __shared__ float sm[];
    float* xbuf = sm + OFF_XBUF;
    float* sW1  = sm + OFF_W1;
    float* sW2  = sm + OFF_W2;
    float* sB1  = sm + OFF_B1;
    float* sB2  = sm + OFF_B2;
    float* gv   = sm + OFF_GV;
    float* outst= sm + OFF_OUT;
    int*   sval = (int*)(sm + OFF_VAL);

    const int tid  = threadIdx.x;
    const int lane = tid & 31;
    const int wid  = tid >> 5;
    const int q4   = blockIdx.x * NPB;    // first node of this block's node set

    // ---- stage weights once per block ----
    {
        // W1: 4 nodes x 256 float4
        #pragma unroll
        for (int i = 0; i < 8; i++) {
            int idx = i * THREADS + tid;          // 0..1023
            int nd = idx >> 8, rest = idx & 255;
            int gk = c_node2gk[q4 + nd];
            ((float4*)sW1)[idx] = W1_4[gk * 256 + rest];
        }
        // W2, b1 (128 floats each), b2 (4)
        {
            int nd = tid >> 5, j = tid & 31;
            int gk = c_node2gk[q4 + nd];
            sW2[tid] = W2[gk * 32 + j];
            sB1[tid] = b1[gk * 32 + j];
            if (tid < NPB) sB2[tid] = b2[c_node2gk[q4 + tid]];
        }
    }
    __syncthreads();

    const int node = q4 + wid;
    const int g    = c_node2g[node];
    const ull* wbase = (const ull*)(sW1 + wid * 1024);
    const ull* b1p   = (const ull*)(sB1 + wid * 32);
    const float bias2 = sB2[wid];

    for (int tile = blockIdx.y; tile < NTILES; tile += GRIDY) {
        const int s0 = tile * TILE;

        // ---- stage x (coalesced read, transposed conflict-free write) ----
        #pragma unroll
        for (int it = 0; it < 32; it++) {
            int idx = it * THREADS + tid;        // 0..4095 float4s
            int s = idx >> 5, r = idx & 31;
            int n = r >> 3, c = r & 7;
            float4 v = h4[((size_t)(s0 + s) * 24 + q4 + n) * 8 + c];
            int base = n * NODE_STRIDE + (c * 4) * P + s;
            xbuf[base        ] = fmaxf(v.x, 0.f);
            xbuf[base +     P] = fmaxf(v.y, 0.f);
            xbuf[base + 2 * P] = fmaxf(v.z, 0.f);
            xbuf[base + 3 * P] = fmaxf(v.w, 0.f);
        }
        // ---- stage valid (768 int4) ----
        #pragma unroll
        for (int i = 0; i < 6; i++) {
            int idx = i * THREADS + tid;
            ((int4*)sval)[idx] = valid4[(size_t)s0 * 6 + idx];
        }
        __syncthreads();

        // ---- group-valid masks: gv[g][s] ----
        #pragma unroll
        for (int i = 0; i < 6; i++) {
            int e = i * THREADS + tid;           // 0..767
            int gg = e >> 7, s = e & 127;
            const int* vr = sval + s * 24;
            int sum = vr[c_members[gg * 4 + 0]] + vr[c_members[gg * 4 + 1]]
                    + vr[c_members[gg * 4 + 2]] + vr[c_members[gg * 4 + 3]];
            gv[gg * TILE + s] = (sum > 0) ? 1.f : 0.f;
        }
        __syncthreads();

        // ---- compute: warp=node, lane handles samples lane,+32,+64,+96 ----
        ull acc0[16], acc1[16], acc2[16], acc3[16];
        #pragma unroll
        for (int j2 = 0; j2 < 16; j2++) {
            ull bb = b1p[j2];
            acc0[j2] = bb; acc1[j2] = bb; acc2[j2] = bb; acc3[j2] = bb;
        }
        const float* xp = xbuf + wid * NODE_STRIDE + lane;

        #pragma unroll 4
        for (int l = 0; l < 32; l++) {
            float xa = xp[l * P];
            float xb = xp[l * P + 32];
            float xc = xp[l * P + 64];
            float xd = xp[l * P + 96];
            ull A = pack2(xa, xa), B = pack2(xb, xb);
            ull C = pack2(xc, xc), D = pack2(xd, xd);
            const ull* wr = wbase + l * 16;
            #pragma unroll
            for (int j2 = 0; j2 < 16; j2++) {
                ull w = wr[j2];
                ffma2(acc0[j2], A, w);
                ffma2(acc1[j2], B, w);
                ffma2(acc2[j2], C, w);
                ffma2(acc3[j2], D, w);
            }
        }

        // ---- layer 2 + mask -> outstage ----
        const float* w2p = sW2 + wid * 32;
        #pragma unroll
        for (int s = 0; s < 4; s++) {
            ull* acc = (s == 0) ? acc0 : (s == 1) ? acc1 : (s == 2) ? acc2 : acc3;
            int smp = lane + s * 32;
            float o = bias2;
            #pragma unroll
            for (int j2 = 0; j2 < 16; j2++) {
                float h0, h1; unpack2(acc[j2], h0, h1);
                o = fmaf(fmaxf(h0, 0.f), w2p[2 * j2], o);
                o = fmaf(fmaxf(h1, 0.f), w2p[2 * j2 + 1], o);
            }
            o *= gv[g * TILE + smp];
            outst[smp * 5 + wid] = o;
        }
        __syncthreads();

        // ---- coalesced output: one float4 (4 nodes) per sample ----
        {
            float4 o4;
            o4.x = outst[tid * 5 + 0];
            o4.y = outst[tid * 5 + 1];
            o4.z = outst[tid * 5 + 2];
            o4.w = outst[tid * 5 + 3];
            *(float4*)(out + ((size_t)(s0 + tid) * 24 + q4)) = o4;
        }
        __syncthreads();   // protect xbuf/sval before next tile's staging
    }
}

extern "C" void kernel_launch(void* const* d_in, const int* in_sizes, int n_in,
                              void* d_out, int out_size) {
    const float4* h4    = (const float4*)d_in[0];
    const int4*   v4    = (const int4*)  d_in[1];
    const float4* W1_4  = (const float4*)d_in[2];
    const float*  b1    = (const float*) d_in[3];
    const float*  W2    = (const float*) d_in[4];
    const float*  b2    = (const float*) d_in[5];
    float* out = (float*)d_out;

    cudaFuncSetAttribute(grouped_mlp_kernel,
                         cudaFuncAttributeMaxDynamicSharedMemorySize, SMEM_BYTES);
    dim3 grid(24 / NPB, GRIDY);   // (6, 256)
    grouped_mlp_kernel<<<grid, THREADS, SMEM_BYTES>>>(h4, v4, W1_4, b1, W2, b2, out);
}

// round 3
// speedup vs baseline: 1.2707x; 1.1334x over previous
#include <cuda_runtime.h>

#define NPB 2                     // nodes per block
#define TILE 128                  // samples per tile
#define THREADS 128               // 4 warps: (node, warp-in-node) = (wid>>1, wid&1)
#define NSAMP 131072
#define NTILES (NSAMP / TILE)     // 1024
#define GRIDY 256                 // -> 4 tiles per block
#define P 129                     // padded floats per l-row
#define NODE_STRIDE (32 * P + 1)  // 4129

typedef unsigned long long ull;

__constant__ int c_node2gk[24] = {0,4,8,1,5,9,2,6,10,3,7,11,12,13,14,15,16,20,17,21,18,22,19,23};
__constant__ int c_node2g[24]  = {0,1,2,0,1,2,0,1,2,0,1,2,3,3,3,3,4,5,4,5,4,5,4,5};
__constant__ int c_members[24] = {0,3,6,9, 1,4,7,10, 2,5,8,11, 12,13,14,15, 16,18,20,22, 17,19,21,23};

// smem float offsets (OFF_W1 16B-aligned for LDS.128)
#define OFF_XBUF 0
#define OFF_W1   8260                       // xbuf = 2*4129 = 8258, padded to 8260
#define OFF_W2   (OFF_W1 + NPB * 1024)      // 10308
#define OFF_B1   (OFF_W2 + NPB * 32)        // 10372
#define OFF_B2   (OFF_B1 + NPB * 32)        // 10436
#define OFF_GV   (OFF_B2 + 4)               // 10440
#define OFF_OUT  (OFF_GV + NPB * TILE)      // 10696
#define SMEM_FLOATS (OFF_OUT + TILE * NPB)  // 10952
#define SMEM_BYTES (SMEM_FLOATS * 4)        // 43808

__device__ __forceinline__ ull pack2(float a, float b) {
    ull r; asm("mov.b64 %0, {%1, %2};" : "=l"(r) : "f"(a), "f"(b)); return r;
}
__device__ __forceinline__ void unpack2(ull v, float &a, float &b) {
    asm("mov.b64 {%0, %1}, %2;" : "=f"(a), "=f"(b) : "l"(v));
}
__device__ __forceinline__ void ffma2(ull &d, ull a, ull b) {
    asm("fma.rn.f32x2 %0, %1, %2, %0;" : "+l"(d) : "l"(a), "l"(b));
}

__global__ __launch_bounds__(THREADS, 4)
void grouped_mlp_kernel(const float4* __restrict__ h4,
                        const int*    __restrict__ valid,
                        const float4* __restrict__ W1_4,
                        const float*  __restrict__ b1,
                        const float*  __restrict__ W2,
                        const float*  __restrict__ b2,
                        float* __restrict__ out)
{
    extern __shared__ float sm[];
    float* xbuf  = sm + OFF_XBUF;
    float* sW1   = sm + OFF_W1;
    float* sW2   = sm + OFF_W2;
    float* sB1   = sm + OFF_B1;
    float* sB2   = sm + OFF_B2;
    float* gv    = sm + OFF_GV;
    float* outst = sm + OFF_OUT;

    const int tid  = threadIdx.x;
    const int lane = tid & 31;
    const int wid  = tid >> 5;
    const int nd   = wid >> 1;          // node within block (0/1)
    const int ww   = wid & 1;           // warp within node
    const int q2   = blockIdx.x * NPB;  // first node of this block

    const int gA = c_node2g[q2];
    const int gB = c_node2g[q2 + 1];

    // ---- stage weights once per block ----
    {
        #pragma unroll
        for (int i = 0; i < (NPB * 256) / THREADS; i++) {   // 4 iters, 512 float4
            int idx = i * THREADS + tid;
            int n = idx >> 8, rest = idx & 255;
            int gk = c_node2gk[q2 + n];
            ((float4*)sW1)[idx] = W1_4[gk * 256 + rest];
        }
        if (tid < NPB * 32) {
            int n = tid >> 5, j = tid & 31;
            int gk = c_node2gk[q2 + n];
            sW2[tid] = W2[gk * 32 + j];
            sB1[tid] = b1[gk * 32 + j];
        }
        if (tid < NPB) sB2[tid] = b2[c_node2gk[q2 + tid]];
    }
    __syncthreads();

    const ulonglong2* wp = (const ulonglong2*)(sW1 + nd * 1024);
    const ull* b1p = (const ull*)(sB1 + nd * 32);
    const float* w2p = sW2 + nd * 32;
    const float bias2 = sB2[nd];

    for (int tile = blockIdx.y; tile < NTILES; tile += GRIDY) {
        const int s0 = tile * TILE;

        // ---- stage x: coalesced gmem read, transposed smem write, fused relu ----
        #pragma unroll
        for (int it = 0; it < (TILE * NPB * 8) / THREADS; it++) {   // 16 iters
            int idx = it * THREADS + tid;          // 0..2047 float4
            int s = idx >> 4, r = idx & 15;
            int n = r >> 3, c = r & 7;
            float4 v = h4[((size_t)(s0 + s) * 24 + q2 + n) * 8 + c];
            int base = n * NODE_STRIDE + (c * 4) * P + s;
            xbuf[base        ] = fmaxf(v.x, 0.f);
            xbuf[base +     P] = fmaxf(v.y, 0.f);
            xbuf[base + 2 * P] = fmaxf(v.z, 0.f);
            xbuf[base + 3 * P] = fmaxf(v.w, 0.f);
        }

        // ---- group-valid masks straight from gmem (L2-resident) ----
        {
            const int* vr = valid + (size_t)(s0 + tid) * 24;
            int a = vr[c_members[gA*4+0]] + vr[c_members[gA*4+1]]
                  + vr[c_members[gA*4+2]] + vr[c_members[gA*4+3]];
            int b = vr[c_members[gB*4+0]] + vr[c_members[gB*4+1]]
                  + vr[c_members[gB*4+2]] + vr[c_members[gB*4+3]];
            gv[tid]        = (a > 0) ? 1.f : 0.f;
            gv[TILE + tid] = (b > 0) ? 1.f : 0.f;
        }
        __syncthreads();

        // ---- compute: warp = (node, sample-half); lane handles 2 samples ----
        ull acc0[16], acc1[16];
        #pragma unroll
        for (int j2 = 0; j2 < 16; j2++) {
            ull bb = b1p[j2];
            acc0[j2] = bb; acc1[j2] = bb;
        }
        const float* xp = xbuf + nd * NODE_STRIDE + ww * 64 + lane;

        #pragma unroll 4
        for (int l = 0; l < 32; l++) {
            float xa = xp[l * P];
            float xb = xp[l * P + 32];
            ull A = pack2(xa, xa), B = pack2(xb, xb);
            #pragma unroll
            for (int j4 = 0; j4 < 8; j4++) {
                ulonglong2 w = wp[l * 8 + j4];   // LDS.128 broadcast
                ffma2(acc0[2*j4  ], A, w.x);
                ffma2(acc0[2*j4+1], A, w.y);
                ffma2(acc1[2*j4  ], B, w.x);
                ffma2(acc1[2*j4+1], B, w.y);
            }
        }

        // ---- layer 2 + mask -> outstage ----
        #pragma unroll
        for (int s = 0; s < 2; s++) {
            ull* acc = s ? acc1 : acc0;
            int smp = ww * 64 + s * 32 + lane;
            float o = bias2;
            #pragma unroll
            for (int j2 = 0; j2 < 16; j2++) {
                float h0, h1; unpack2(acc[j2], h0, h1);
                o = fmaf(fmaxf(h0, 0.f), w2p[2*j2  ], o);
                o = fmaf(fmaxf(h1, 0.f), w2p[2*j2+1], o);
            }
            o *= gv[nd * TILE + smp];
            outst[smp * NPB + nd] = o;
        }
        __syncthreads();

        // ---- coalesced-ish output: float2 (2 nodes) per sample ----
        {
            float2 o2;
            o2.x = outst[tid * 2 + 0];
            o2.y = outst[tid * 2 + 1];
            *(float2*)(out + ((size_t)(s0 + tid) * 24 + q2)) = o2;
        }
        __syncthreads();   // protect xbuf/outst before next tile
    }
}

extern "C" void kernel_launch(void* const* d_in, const int* in_sizes, int n_in,
                              void* d_out, int out_size) {
    const float4* h4    = (const float4*)d_in[0];
    const int*    valid = (const int*)   d_in[1];
    const float4* W1_4  = (const float4*)d_in[2];
    const float*  b1    = (const float*) d_in[3];
    const float*  W2    = (const float*) d_in[4];
    const float*  b2    = (const float*) d_in[5];
    float* out = (float*)d_out;

    cudaFuncSetAttribute(grouped_mlp_kernel,
                         cudaFuncAttributeMaxDynamicSharedMemorySize, SMEM_BYTES);
    dim3 grid(24 / NPB, GRIDY);   // (12, 256)
    grouped_mlp_kernel<<<grid, THREADS, SMEM_BYTES>>>(h4, valid, W1_4, b1, W2, b2, out);
}

// round 5
// speedup vs baseline: 1.5314x; 1.2052x over previous
#include <cuda_runtime.h>
#include <cstdint>

#define NSAMP   131072
#define TILE    128
#define NTILES  (NSAMP / TILE)     // 1024
#define YBLKS   32
#define TPC     (NTILES / YBLKS)   // 32
#define THREADS 128

__device__ float d_gv[6 * NSAMP];

__constant__ int c_node2gk[24] = {0,4,8,1,5,9,2,6,10,3,7,11,12,13,14,15,16,20,17,21,18,22,19,23};
__constant__ int c_node2g[24]  = {0,1,2,0,1,2,0,1,2,0,1,2,3,3,3,3,4,5,4,5,4,5,4,5};
__constant__ int c_members[24] = {0,3,6,9, 1,4,7,10, 2,5,8,11, 12,13,14,15, 16,18,20,22, 17,19,21,23};

__device__ __forceinline__ uint32_t tf32_rna(float x) {
    uint32_t r; asm("cvt.rna.tf32.f32 %0, %1;" : "=r"(r) : "f"(x)); return r;
}

#define MMA_TF32(d, a0, a1, a2, a3, b0, b1)                                   \
    asm volatile(                                                             \
        "mma.sync.aligned.m16n8k8.row.col.f32.tf32.tf32.f32 "                 \
        "{%0,%1,%2,%3}, {%4,%5,%6,%7}, {%8,%9}, {%0,%1,%2,%3};"               \
        : "+f"(d[0]), "+f"(d[1]), "+f"(d[2]), "+f"(d[3])                      \
        : "r"(a0), "r"(a1), "r"(a2), "r"(a3), "r"(b0), "r"(b1))

// ---------------- gv pre-kernel ----------------
__global__ void gv_kernel(const int4* __restrict__ v4) {
    __shared__ int sval[TILE * 24];
    const int tid = threadIdx.x;
    const int s0  = blockIdx.x * TILE;
    #pragma unroll
    for (int i = 0; i < 6; i++)
        ((int4*)sval)[i * THREADS + tid] = v4[(size_t)s0 * 6 + i * THREADS + tid];
    __syncthreads();
    const int* vr = sval + tid * 24;
    #pragma unroll
    for (int g = 0; g < 6; g++) {
        int a = vr[c_members[g*4+0]] + vr[c_members[g*4+1]]
              + vr[c_members[g*4+2]] + vr[c_members[g*4+3]];
        d_gv[g * NSAMP + s0 + tid] = (a > 0) ? 1.f : 0.f;
    }
}

// ---------------- main kernel ----------------
__global__ __launch_bounds__(THREADS)
void mlp_mma_kernel(const float4* __restrict__ h4,
                    const float*  __restrict__ W1,
                    const float*  __restrict__ b1,
                    const float*  __restrict__ W2,
                    const float*  __restrict__ b2,
                    float* __restrict__ out)
{
    __shared__ __align__(128) float xbuf[TILE * 32];   // 16 KB, SW128-swizzled

    const int tid  = threadIdx.x;
    const int lane = tid & 31;
    const int w    = tid >> 5;          // warp 0..3 -> rows w*32..w*32+31
    const int t    = lane & 3;          // threadID_in_group
    const int g    = lane >> 2;         // groupID (0..7)
    const int node = blockIdx.x;
    const int gk   = c_node2gk[node];
    const int grp  = c_node2g[node];

    // ---- B fragments (weights), resident for whole kernel ----
    // B[k][n] = W1[k][n]; b0: (row=k0+t, col=n0+g), b1: (row=k0+t+4, col=n0+g)
    uint32_t bhi[4][4][2], blo[4][4][2];
    {
        const float* wp = W1 + (size_t)gk * 1024;
        #pragma unroll
        for (int kf = 0; kf < 4; kf++)
            #pragma unroll
            for (int nf = 0; nf < 4; nf++) {
                float w0 = wp[(kf*8 + t    ) * 32 + nf*8 + g];
                float w1 = wp[(kf*8 + t + 4) * 32 + nf*8 + g];
                uint32_t h0 = tf32_rna(w0), h1 = tf32_rna(w1);
                bhi[kf][nf][0] = h0;
                bhi[kf][nf][1] = h1;
                blo[kf][nf][0] = tf32_rna(w0 - __uint_as_float(h0));
                blo[kf][nf][1] = tf32_rna(w1 - __uint_as_float(h1));
            }
    }
    // per-thread epilogue constants: cols {nf*8 + 2t, +1}
    float b1c[8], w2c[8];
    #pragma unroll
    for (int nf = 0; nf < 4; nf++) {
        int col = nf * 8 + 2 * t;
        b1c[2*nf  ] = b1[gk * 32 + col];
        b1c[2*nf+1] = b1[gk * 32 + col + 1];
        w2c[2*nf  ] = W2[gk * 32 + col];
        w2c[2*nf+1] = W2[gk * 32 + col + 1];
    }
    const float bias2 = b2[gk];

    // row bookkeeping: 4 rows per thread (2 m-frags x 2 halves)
    int rowl[4];
    rowl[0] = w * 32 + g;       rowl[1] = rowl[0] + 8;
    rowl[2] = rowl[0] + 16;     rowl[3] = rowl[0] + 24;
    int rbase[4], rmask[4];
    #pragma unroll
    for (int i = 0; i < 4; i++) {
        rbase[i] = rowl[i] * 32;             // float index of row start
        rmask[i] = (rowl[i] & 7) << 2;       // XOR mask in float units (bits 2-4 of byte>>2)
    }

    // prefetch tile 0
    float4 xr[8];
    {
        int s0 = blockIdx.y * TILE;
        #pragma unroll
        for (int i = 0; i < 8; i++) {
            int idx = i * THREADS + tid, s = idx >> 3, c = idx & 7;
            xr[i] = h4[((size_t)(s0 + s) * 24 + node) * 8 + c];
        }
    }

    for (int it = 0; it < TPC; it++) {
        const int s0 = (blockIdx.y + it * YBLKS) * TILE;

        // ---- stage: relu + swizzled STS.128 ----
        #pragma unroll
        for (int i = 0; i < 8; i++) {
            int idx = i * THREADS + tid, s = idx >> 3, c = idx & 7;
            float4 v = xr[i];
            v.x = fmaxf(v.x, 0.f); v.y = fmaxf(v.y, 0.f);
            v.z = fmaxf(v.z, 0.f); v.w = fmaxf(v.w, 0.f);
            int foff = s * 32 + ((c * 4) ^ ((s & 7) << 2));   // float units
            *(float4*)(xbuf + foff) = v;
        }
        __syncthreads();

        // prefetch next tile (overlaps compute)
        if (it + 1 < TPC) {
            int sn = (blockIdx.y + (it + 1) * YBLKS) * TILE;
            #pragma unroll
            for (int i = 0; i < 8; i++) {
                int idx = i * THREADS + tid, s = idx >> 3, c = idx & 7;
                xr[i] = h4[((size_t)(sn + s) * 24 + node) * 8 + c];
            }
        }

        // ---- mainloop: D[mf][nf][4] over 4 k-frags, 3 split terms ----
        float dd[2][4][4];
        #pragma unroll
        for (int mf = 0; mf < 2; mf++)
            #pragma unroll
            for (int nf = 0; nf < 4; nf++)
                #pragma unroll
                for (int i = 0; i < 4; i++) dd[mf][nf][i] = 0.f;

        #pragma unroll
        for (int kf = 0; kf < 4; kf++) {
            int c0 = kf * 8 + t;        // a0/a1 col
            uint32_t ahi[2][4], alo[2][4];
            #pragma unroll
            for (int mf = 0; mf < 2; mf++) {
                #pragma unroll
                for (int half = 0; half < 2; half++) {       // a0/a1 then a2/a3
                    int ri = mf * 2 + half;
                    float v0 = xbuf[rbase[ri] + ((c0    ) ^ rmask[ri])];
                    float v1 = xbuf[rbase[ri] + ((c0 + 4) ^ rmask[ri])];
                    uint32_t h0 = tf32_rna(v0), h1 = tf32_rna(v1);
                    ahi[mf][half    ] = h0;
                    ahi[mf][half + 2] = h1;
                    alo[mf][half    ] = tf32_rna(v0 - __uint_as_float(h0));
                    alo[mf][half + 2] = tf32_rna(v1 - __uint_as_float(h1));
                }
            }
            #pragma unroll
            for (int nf = 0; nf < 4; nf++)
                #pragma unroll
                for (int mf = 0; mf < 2; mf++) {
                    MMA_TF32(dd[mf][nf], ahi[mf][0], ahi[mf][1], ahi[mf][2], ahi[mf][3],
                             bhi[kf][nf][0], bhi[kf][nf][1]);
                    MMA_TF32(dd[mf][nf], ahi[mf][0], ahi[mf][1], ahi[mf][2], ahi[mf][3],
                             blo[kf][nf][0], blo[kf][nf][1]);
                    MMA_TF32(dd[mf][nf], alo[mf][0], alo[mf][1], alo[mf][2], alo[mf][3],
                             bhi[kf][nf][0], bhi[kf][nf][1]);
                }
        }

        // ---- epilogue: +b1, relu, dot W2, lane-quad reduce, mask, store ----
        #pragma unroll
        for (int mf = 0; mf < 2; mf++) {
            float p0 = 0.f, p1 = 0.f;
            #pragma unroll
            for (int nf = 0; nf < 4; nf++) {
                p0 = fmaf(fmaxf(dd[mf][nf][0] + b1c[2*nf  ], 0.f), w2c[2*nf  ], p0);
                p0 = fmaf(fmaxf(dd[mf][nf][1] + b1c[2*nf+1], 0.f), w2c[2*nf+1], p0);
                p1 = fmaf(fmaxf(dd[mf][nf][2] + b1c[2*nf  ], 0.f), w2c[2*nf  ], p1);
                p1 = fmaf(fmaxf(dd[mf][nf][3] + b1c[2*nf+1], 0.f), w2c[2*nf+1], p1);
            }
            p0 += __shfl_xor_sync(0xFFFFFFFF, p0, 1);
            p0 += __shfl_xor_sync(0xFFFFFFFF, p0, 2);
            p1 += __shfl_xor_sync(0xFFFFFFFF, p1, 1);
            p1 += __shfl_xor_sync(0xFFFFFFFF, p1, 2);
            if (t == 0) {
                int sA = s0 + w * 32 + mf * 16 + g;
                int sB = sA + 8;
                float gA = d_gv[grp * NSAMP + sA];
                float gB = d_gv[grp * NSAMP + sB];
                out[(size_t)sA * 24 + node] = (p0 + bias2) * gA;
                out[(size_t)sB * 24 + node] = (p1 + bias2) * gB;
            }
        }
        __syncthreads();   // xbuf reusable
    }
}

extern "C" void kernel_launch(void* const* d_in, const int* in_sizes, int n_in,
                              void* d_out, int out_size) {
    const float4* h4 = (const float4*)d_in[0];
    const int4*   v4 = (const int4*)  d_in[1];
    const float*  W1 = (const float*) d_in[2];
    const float*  b1 = (const float*) d_in[3];
    const float*  W2 = (const float*) d_in[4];
    const float*  b2 = (const float*) d_in[5];
    float* out = (float*)d_out;

    gv_kernel<<<NTILES, THREADS>>>(v4);
    dim3 grid(24, YBLKS);   // 768 CTAs
    mlp_mma_kernel<<<grid, THREADS>>>(h4, W1, b1, W2, b2, out);
}

// round 6
// speedup vs baseline: 1.7701x; 1.1559x over previous
#include <cuda_runtime.h>
#include <cstdint>

#define NSAMP   131072
#define TILE    128
#define NTILES  (NSAMP / TILE)     // 1024
#define YB      24                 // y-slices -> 576 CTAs
#define THREADS 128

__device__ float d_gv[6 * NSAMP];

__constant__ int c_node2gk[24] = {0,4,8,1,5,9,2,6,10,3,7,11,12,13,14,15,16,20,17,21,18,22,19,23};
__constant__ int c_node2g[24]  = {0,1,2,0,1,2,0,1,2,0,1,2,3,3,3,3,4,5,4,5,4,5,4,5};
__constant__ int c_members[24] = {0,3,6,9, 1,4,7,10, 2,5,8,11, 12,13,14,15, 16,18,20,22, 17,19,21,23};

__device__ __forceinline__ uint32_t tf32_rna(float x) {
    uint32_t r; asm("cvt.rna.tf32.f32 %0, %1;" : "=r"(r) : "f"(x)); return r;
}
__device__ __forceinline__ uint32_t smem_u32(const void* p) {
    uint32_t a;
    asm("{ .reg .u64 t; cvta.to.shared.u64 t, %1; cvt.u32.u64 %0, t; }" : "=r"(a) : "l"(p));
    return a;
}
#define CP_ASYNC16(dst, src) \
    asm volatile("cp.async.cg.shared.global [%0], [%1], 16;" :: "r"(dst), "l"(src) : "memory")
#define CP_COMMIT()  asm volatile("cp.async.commit_group;" ::: "memory")
#define CP_WAIT(n)   asm volatile("cp.async.wait_group %0;" :: "n"(n) : "memory")

#define MMA_TF32(d, a0, a1, a2, a3, b0, b1)                                   \
    asm volatile(                                                             \
        "mma.sync.aligned.m16n8k8.row.col.f32.tf32.tf32.f32 "                 \
        "{%0,%1,%2,%3}, {%4,%5,%6,%7}, {%8,%9}, {%0,%1,%2,%3};"               \
        : "+f"(d[0]), "+f"(d[1]), "+f"(d[2]), "+f"(d[3])                      \
        : "r"(a0), "r"(a1), "r"(a2), "r"(a3), "r"(b0), "r"(b1))

// ---------------- gv pre-kernel ----------------
__global__ void gv_kernel(const int4* __restrict__ v4) {
    __shared__ int sval[TILE * 24];
    const int tid = threadIdx.x;
    const int s0  = blockIdx.x * TILE;
    #pragma unroll
    for (int i = 0; i < 6; i++)
        ((int4*)sval)[i * THREADS + tid] = v4[(size_t)s0 * 6 + i * THREADS + tid];
    __syncthreads();
    const int* vr = sval + tid * 24;
    #pragma unroll
    for (int g = 0; g < 6; g++) {
        int a = vr[c_members[g*4+0]] + vr[c_members[g*4+1]]
              + vr[c_members[g*4+2]] + vr[c_members[g*4+3]];
        d_gv[g * NSAMP + s0 + tid] = (a > 0) ? 1.f : 0.f;
    }
}

// ---------------- main kernel ----------------
__global__ __launch_bounds__(THREADS, 4)
void mlp_mma_kernel(const float4* __restrict__ h4,
                    const float*  __restrict__ W1,
                    const float*  __restrict__ b1,
                    const float*  __restrict__ W2,
                    const float*  __restrict__ b2,
                    float* __restrict__ out)
{
    __shared__ __align__(128) float xbuf[2][TILE * 32];   // 32 KB double buffer
    __shared__ float sWlo[4][4][32][2];                    // 4 KB lo-weight frags
    __shared__ float sB1[32], sW2[32], sB2;

    const int tid  = threadIdx.x;
    const int lane = tid & 31;
    const int w    = tid >> 5;
    const int t    = lane & 3;
    const int g    = lane >> 2;
    const int node = blockIdx.x;
    const int gk   = c_node2gk[node];
    const int grp  = c_node2g[node];

    // ---- B hi fragments in regs; lo fragments to smem ----
    uint32_t bhi[4][4][2];
    {
        const float* wp = W1 + (size_t)gk * 1024;
        #pragma unroll
        for (int kf = 0; kf < 4; kf++)
            #pragma unroll
            for (int nf = 0; nf < 4; nf++) {
                float w0 = wp[(kf*8 + t    ) * 32 + nf*8 + g];
                float w1 = wp[(kf*8 + t + 4) * 32 + nf*8 + g];
                uint32_t h0 = tf32_rna(w0), h1 = tf32_rna(w1);
                bhi[kf][nf][0] = h0;
                bhi[kf][nf][1] = h1;
                sWlo[kf][nf][lane][0] =
                    __uint_as_float(tf32_rna(w0 - __uint_as_float(h0)));
                sWlo[kf][nf][lane][1] =
                    __uint_as_float(tf32_rna(w1 - __uint_as_float(h1)));
            }
        if (tid < 32) {
            sB1[tid] = b1[gk * 32 + tid];
            sW2[tid] = W2[gk * 32 + tid];
        }
        if (tid == 0) sB2 = b2[gk];
    }

    // per-thread smem byte bases
    const uint32_t xb0 = smem_u32(&xbuf[0][0]);
    const uint32_t xb1 = smem_u32(&xbuf[1][0]);

    // copy-index precompute: 8 chunks of 16B per thread
    // idx = i*128+tid -> s = idx>>3, c = idx&7
    // dst byte off = s*128 + ((c*16) ^ ((s&7)<<4))
    int cp_s[8]; uint32_t cp_doff[8];
    #pragma unroll
    for (int i = 0; i < 8; i++) {
        int idx = i * THREADS + tid, s = idx >> 3, c = idx & 7;
        cp_s[i] = s;
        cp_doff[i] = (uint32_t)(s * 128 + ((c * 16) ^ ((s & 7) << 4)));
    }

    // fragment-load float offsets (within a buffer), loop-invariant
    int rowl[4];
    rowl[0] = w * 32 + g; rowl[1] = rowl[0] + 8;
    rowl[2] = rowl[0] + 16; rowl[3] = rowl[0] + 24;
    int aoff[4][4][2];   // [kf][ri][pair]
    #pragma unroll
    for (int kf = 0; kf < 4; kf++)
        #pragma unroll
        for (int ri = 0; ri < 4; ri++) {
            int rm = (rowl[ri] & 7) << 2;
            aoff[kf][ri][0] = rowl[ri] * 32 + ((kf * 8 + t    ) ^ rm);
            aoff[kf][ri][1] = rowl[ri] * 32 + ((kf * 8 + t + 4) ^ rm);
        }

    __syncthreads();   // sWlo/sB1/sW2 ready

    // ---- prologue: copy tile y into buf 0 ----
    int tcur = blockIdx.y;
    {
        const char* src0 = (const char*)(h4 + ((size_t)tcur * TILE * 24 + node) * 8);
        #pragma unroll
        for (int i = 0; i < 8; i++)
            CP_ASYNC16(xb0 + cp_doff[i], src0 + (size_t)cp_s[i] * 3072
                                              + (cp_doff[i] & 127 ? 0 : 0)
                                              + (( (i*THREADS+tid) & 7) * 16));
        CP_COMMIT();
    }

    int p = 0;
    while (tcur < NTILES) {
        const int tnext = tcur + YB;
        if (tnext < NTILES) {
            uint32_t xbn = (p ^ 1) ? xb1 : xb0;
            const char* srcn = (const char*)(h4 + ((size_t)tnext * TILE * 24 + node) * 8);
            #pragma unroll
            for (int i = 0; i < 8; i++)
                CP_ASYNC16(xbn + cp_doff[i],
                           srcn + (size_t)cp_s[i] * 3072 + (((i*THREADS+tid) & 7) * 16));
            CP_COMMIT();
            CP_WAIT(1);
        } else {
            CP_WAIT(0);
        }
        __syncthreads();   // current buffer visible to all

        const float* xb = p ? xbuf[1] : xbuf[0];

        // ---- mainloop ----
        float dd[2][4][4];
        #pragma unroll
        for (int mf = 0; mf < 2; mf++)
            #pragma unroll
            for (int nf = 0; nf < 4; nf++)
                #pragma unroll
                for (int i = 0; i < 4; i++) dd[mf][nf][i] = 0.f;

        #pragma unroll
        for (int kf = 0; kf < 4; kf++) {
            uint32_t ahi[2][4], alo[2][4];
            #pragma unroll
            for (int mf = 0; mf < 2; mf++)
                #pragma unroll
                for (int half = 0; half < 2; half++) {
                    int ri = mf * 2 + half;
                    float v0 = fmaxf(xb[aoff[kf][ri][0]], 0.f);
                    float v1 = fmaxf(xb[aoff[kf][ri][1]], 0.f);
                    uint32_t h0 = tf32_rna(v0), h1 = tf32_rna(v1);
                    ahi[mf][half    ] = h0;
                    ahi[mf][half + 2] = h1;
                    alo[mf][half    ] = tf32_rna(v0 - __uint_as_float(h0));
                    alo[mf][half + 2] = tf32_rna(v1 - __uint_as_float(h1));
                }
            #pragma unroll
            for (int nf = 0; nf < 4; nf++) {
                float2 wl = *(const float2*)&sWlo[kf][nf][lane][0];
                uint32_t bl0 = __float_as_uint(wl.x), bl1 = __float_as_uint(wl.y);
                #pragma unroll
                for (int mf = 0; mf < 2; mf++) {
                    MMA_TF32(dd[mf][nf], ahi[mf][0], ahi[mf][1], ahi[mf][2], ahi[mf][3],
                             bhi[kf][nf][0], bhi[kf][nf][1]);
                    MMA_TF32(dd[mf][nf], ahi[mf][0], ahi[mf][1], ahi[mf][2], ahi[mf][3],
                             bl0, bl1);
                    MMA_TF32(dd[mf][nf], alo[mf][0], alo[mf][1], alo[mf][2], alo[mf][3],
                             bhi[kf][nf][0], bhi[kf][nf][1]);
                }
            }
        }

        // ---- epilogue ----
        const int s0 = tcur * TILE;
        const float bias2 = sB2;
        #pragma unroll
        for (int mf = 0; mf < 2; mf++) {
            float p0 = 0.f, p1 = 0.f;
            #pragma unroll
            for (int nf = 0; nf < 4; nf++) {
                int col = nf * 8 + 2 * t;
                float bA = sB1[col], bB = sB1[col + 1];
                float wA = sW2[col], wB = sW2[col + 1];
                p0 = fmaf(fmaxf(dd[mf][nf][0] + bA, 0.f), wA, p0);
                p0 = fmaf(fmaxf(dd[mf][nf][1] + bB, 0.f), wB, p0);
                p1 = fmaf(fmaxf(dd[mf][nf][2] + bA, 0.f), wA, p1);
                p1 = fmaf(fmaxf(dd[mf][nf][3] + bB, 0.f), wB, p1);
            }
            p0 += __shfl_xor_sync(0xFFFFFFFF, p0, 1);
            p0 += __shfl_xor_sync(0xFFFFFFFF, p0, 2);
            p1 += __shfl_xor_sync(0xFFFFFFFF, p1, 1);
            p1 += __shfl_xor_sync(0xFFFFFFFF, p1, 2);
            if (t == 0) {
                int sA = s0 + w * 32 + mf * 16 + g;
                int sB = sA + 8;
                float gA = d_gv[grp * NSAMP + sA];
                float gB = d_gv[grp * NSAMP + sB];
                out[(size_t)sA * 24 + node] = (p0 + bias2) * gA;
                out[(size_t)sB * 24 + node] = (p1 + bias2) * gB;
            }
        }
        __syncthreads();   // buffer p consumed; safe to refill in 2 iterations
        p ^= 1;
        tcur = tnext;
    }
}

extern "C" void kernel_launch(void* const* d_in, const int* in_sizes, int n_in,
                              void* d_out, int out_size) {
    const float4* h4 = (const float4*)d_in[0];
    const int4*   v4 = (const int4*)  d_in[1];
    const float*  W1 = (const float*) d_in[2];
    const float*  b1 = (const float*) d_in[3];
    const float*  W2 = (const float*) d_in[4];
    const float*  b2 = (const float*) d_in[5];
    float* out = (float*)d_out;

    gv_kernel<<<NTILES, THREADS>>>(v4);
    dim3 grid(24, YB);   // 576 CTAs, single wave at 4 CTAs/SM
    mlp_mma_kernel<<<grid, THREADS>>>(h4, W1, b1, W2, b2, out);
}

// round 7
// speedup vs baseline: 2.4513x; 1.3848x over previous
#include <cuda_runtime.h>
#include <cuda_fp16.h>
#include <cstdint>

#define NSAMP   131072
#define TILE    128
#define NTILES  (NSAMP / TILE)     // 1024
#define YB      24                 // 576 CTAs, 4/SM single wave
#define THREADS 128

__device__ float d_gv[6 * NSAMP];

__constant__ int c_node2gk[24] = {0,4,8,1,5,9,2,6,10,3,7,11,12,13,14,15,16,20,17,21,18,22,19,23};
__constant__ int c_node2g[24]  = {0,1,2,0,1,2,0,1,2,0,1,2,3,3,3,3,4,5,4,5,4,5,4,5};
__constant__ int c_members[24] = {0,3,6,9, 1,4,7,10, 2,5,8,11, 12,13,14,15, 16,18,20,22, 17,19,21,23};

__device__ __forceinline__ uint32_t smem_u32(const void* p) {
    uint32_t a;
    asm("{ .reg .u64 t; cvta.to.shared.u64 t, %1; cvt.u32.u64 %0, t; }" : "=r"(a) : "l"(p));
    return a;
}
__device__ __forceinline__ uint32_t h2u(__half2 h) {
    uint32_t u; __builtin_memcpy(&u, &h, 4); return u;
}

#define LDMX4(r0, r1, r2, r3, addr)                                           \
    asm volatile("ldmatrix.sync.aligned.m8n8.x4.shared.b16 {%0,%1,%2,%3}, [%4];" \
        : "=r"(r0), "=r"(r1), "=r"(r2), "=r"(r3) : "r"(addr))

#define MMA_F16(d, a0, a1, a2, a3, b0, b1)                                    \
    asm volatile(                                                             \
        "mma.sync.aligned.m16n8k16.row.col.f32.f16.f16.f32 "                  \
        "{%0,%1,%2,%3}, {%4,%5,%6,%7}, {%8,%9}, {%0,%1,%2,%3};"               \
        : "+f"(d[0]), "+f"(d[1]), "+f"(d[2]), "+f"(d[3])                      \
        : "r"(a0), "r"(a1), "r"(a2), "r"(a3), "r"(b0), "r"(b1))

// ---------------- gv pre-kernel ----------------
__global__ void gv_kernel(const int4* __restrict__ v4) {
    __shared__ int sval[TILE * 24];
    const int tid = threadIdx.x;
    const int s0  = blockIdx.x * TILE;
    #pragma unroll
    for (int i = 0; i < 6; i++)
        ((int4*)sval)[i * THREADS + tid] = v4[(size_t)s0 * 6 + i * THREADS + tid];
    __syncthreads();
    const int* vr = sval + tid * 24;
    #pragma unroll
    for (int g = 0; g < 6; g++) {
        int a = vr[c_members[g*4+0]] + vr[c_members[g*4+1]]
              + vr[c_members[g*4+2]] + vr[c_members[g*4+3]];
        d_gv[g * NSAMP + s0 + tid] = (a > 0) ? 1.f : 0.f;
    }
}

// ---------------- main kernel ----------------
__global__ __launch_bounds__(THREADS, 4)
void mlp_mma_kernel(const float4* __restrict__ h4,
                    const float*  __restrict__ W1,
                    const float*  __restrict__ b1,
                    const float*  __restrict__ W2,
                    const float*  __restrict__ b2,
                    float* __restrict__ out)
{
    // X tiles as fp16: 128 rows x 32 halves (64B rows), hi then lo
    __shared__ __align__(128) char xhi[TILE * 64];
    __shared__ __align__(128) char xlo[TILE * 64];
    __shared__ float sB1[32], sW2[32], sB2;

    const int tid  = threadIdx.x;
    const int lane = tid & 31;
    const int w    = tid >> 5;
    const int t    = lane & 3;
    const int g    = lane >> 2;
    const int node = blockIdx.x;
    const int gk   = c_node2gk[node];
    const int grp  = c_node2g[node];

    // ---- B fragments (fp16 hi/lo), resident in regs ----
    // m16n8k16 col-B: b0 = {B[2t][g'], B[2t+1][g']}, b1 = {B[2t+8][g'], B[2t+9][g']}
    uint32_t bhi[2][4][2], blo[2][4][2];
    {
        const float* wp = W1 + (size_t)gk * 1024;
        #pragma unroll
        for (int kf = 0; kf < 2; kf++)
            #pragma unroll
            for (int nf = 0; nf < 4; nf++) {
                int col = nf * 8 + g;
                #pragma unroll
                for (int r = 0; r < 2; r++) {
                    float w0 = wp[(kf*16 + 2*t + 8*r    ) * 32 + col];
                    float w1 = wp[(kf*16 + 2*t + 8*r + 1) * 32 + col];
                    __half2 hh = __floats2half2_rn(w0, w1);
                    float r0 = w0 - __low2float(hh);
                    float r1 = w1 - __high2float(hh);
                    bhi[kf][nf][r] = h2u(hh);
                    blo[kf][nf][r] = h2u(__floats2half2_rn(r0, r1));
                }
            }
        if (tid < 32) {
            sB1[tid] = b1[gk * 32 + tid];
            sW2[tid] = W2[gk * 32 + tid];
        }
        if (tid == 0) sB2 = b2[gk];
    }

    const uint32_t xhib = smem_u32(xhi);
    const uint32_t xlob = smem_u32(xlo);

    // ---- ldmatrix addresses: lane -> (row, 16B chunk), swizzle c^=((r>>1)&3) ----
    // For (mf, kf): row = w*32 + mf*16 + (lane&15); chunk = 2*kf + (lane>>4)
    uint32_t lmoff[2][2];
    {
        int rl = lane & 15, hi16 = (lane >> 4) & 1;
        #pragma unroll
        for (int mf = 0; mf < 2; mf++)
            #pragma unroll
            for (int kf = 0; kf < 2; kf++) {
                int r = w * 32 + mf * 16 + rl;
                int cs = (2 * kf + hi16) ^ ((r >> 1) & 3);
                lmoff[mf][kf] = (uint32_t)(r * 64 + cs * 16);
            }
    }
    // ---- STS offsets: idx=i*128+tid -> s=idx>>3, c=idx&7 (8B units) ----
    uint32_t stoff[8];
    #pragma unroll
    for (int i = 0; i < 8; i++) {
        int idx = i * THREADS + tid, s = idx >> 3, c = idx & 7;
        stoff[i] = (uint32_t)(s * 64 + (((c >> 1) ^ ((s >> 1) & 3)) << 4) + ((c & 1) << 3));
    }

    __syncthreads();

    // ---- prefetch tile 0 ----
    float4 xr[8];
    int tcur = blockIdx.y;
    {
        const float4* src = h4 + ((size_t)tcur * TILE * 24 + node) * 8;
        #pragma unroll
        for (int i = 0; i < 8; i++) {
            int idx = i * THREADS + tid;
            xr[i] = src[(size_t)(idx >> 3) * 192 + (idx & 7)];
        }
    }

    while (tcur < NTILES) {
        // ---- stage: relu + fp16 split + swizzled STS ----
        #pragma unroll
        for (int i = 0; i < 8; i++) {
            float4 v = xr[i];
            v.x = fmaxf(v.x, 0.f); v.y = fmaxf(v.y, 0.f);
            v.z = fmaxf(v.z, 0.f); v.w = fmaxf(v.w, 0.f);
            __half2 h01 = __floats2half2_rn(v.x, v.y);
            __half2 h23 = __floats2half2_rn(v.z, v.w);
            float l0 = v.x - __low2float(h01), l1 = v.y - __high2float(h01);
            float l2 = v.z - __low2float(h23), l3 = v.w - __high2float(h23);
            uint2 hv = make_uint2(h2u(h01), h2u(h23));
            uint2 lv = make_uint2(h2u(__floats2half2_rn(l0, l1)),
                                  h2u(__floats2half2_rn(l2, l3)));
            *(uint2*)(xhi + stoff[i]) = hv;
            *(uint2*)(xlo + stoff[i]) = lv;
        }
        __syncthreads();

        const int tnext = tcur + YB;
        // prefetch next tile (overlaps MMAs)
        if (tnext < NTILES) {
            const float4* src = h4 + ((size_t)tnext * TILE * 24 + node) * 8;
            #pragma unroll
            for (int i = 0; i < 8; i++) {
                int idx = i * THREADS + tid;
                xr[i] = src[(size_t)(idx >> 3) * 192 + (idx & 7)];
            }
        }

        // ---- mainloop ----
        float dd[2][4][4];
        #pragma unroll
        for (int mf = 0; mf < 2; mf++)
            #pragma unroll
            for (int nf = 0; nf < 4; nf++)
                #pragma unroll
                for (int i = 0; i < 4; i++) dd[mf][nf][i] = 0.f;

        #pragma unroll
        for (int kf = 0; kf < 2; kf++) {
            uint32_t ah[2][4], al[2][4];
            #pragma unroll
            for (int mf = 0; mf < 2; mf++) {
                LDMX4(ah[mf][0], ah[mf][1], ah[mf][2], ah[mf][3], xhib + lmoff[mf][kf]);
                LDMX4(al[mf][0], al[mf][1], al[mf][2], al[mf][3], xlob + lmoff[mf][kf]);
            }
            #pragma unroll
            for (int nf = 0; nf < 4; nf++)
                #pragma unroll
                for (int mf = 0; mf < 2; mf++) {
                    MMA_F16(dd[mf][nf], ah[mf][0], ah[mf][1], ah[mf][2], ah[mf][3],
                            bhi[kf][nf][0], bhi[kf][nf][1]);
                    MMA_F16(dd[mf][nf], ah[mf][0], ah[mf][1], ah[mf][2], ah[mf][3],
                            blo[kf][nf][0], blo[kf][nf][1]);
                    MMA_F16(dd[mf][nf], al[mf][0], al[mf][1], al[mf][2], al[mf][3],
                            bhi[kf][nf][0], bhi[kf][nf][1]);
                }
        }

        // ---- epilogue: +b1, relu, dot W2, quad reduce, mask, store ----
        const int s0 = tcur * TILE;
        const float bias2 = sB2;
        #pragma unroll
        for (int mf = 0; mf < 2; mf++) {
            float p0 = 0.f, p1 = 0.f;
            #pragma unroll
            for (int nf = 0; nf < 4; nf++) {
                int col = nf * 8 + 2 * t;
                float bA = sB1[col], bB = sB1[col + 1];
                float wA = sW2[col], wB = sW2[col + 1];
                p0 = fmaf(fmaxf(dd[mf][nf][0] + bA, 0.f), wA, p0);
                p0 = fmaf(fmaxf(dd[mf][nf][1] + bB, 0.f), wB, p0);
                p1 = fmaf(fmaxf(dd[mf][nf][2] + bA, 0.f), wA, p1);
                p1 = fmaf(fmaxf(dd[mf][nf][3] + bB, 0.f), wB, p1);
            }
            p0 += __shfl_xor_sync(0xFFFFFFFF, p0, 1);
            p0 += __shfl_xor_sync(0xFFFFFFFF, p0, 2);
            p1 += __shfl_xor_sync(0xFFFFFFFF, p1, 1);
            p1 += __shfl_xor_sync(0xFFFFFFFF, p1, 2);
            if (t == 0) {
                int sA = s0 + w * 32 + mf * 16 + g;
                int sB = sA + 8;
                float gA = d_gv[grp * NSAMP + sA];
                float gB = d_gv[grp * NSAMP + sB];
                out[(size_t)sA * 24 + node] = (p0 + bias2) * gA;
                out[(size_t)sB * 24 + node] = (p1 + bias2) * gB;
            }
        }
        __syncthreads();   // x buffers reusable
        tcur = tnext;
    }
}

extern "C" void kernel_launch(void* const* d_in, const int* in_sizes, int n_in,
                              void* d_out, int out_size) {
    const float4* h4 = (const float4*)d_in[0];
    const int4*   v4 = (const int4*)  d_in[1];
    const float*  W1 = (const float*) d_in[2];
    const float*  b1 = (const float*) d_in[3];
    const float*  W2 = (const float*) d_in[4];
    const float*  b2 = (const float*) d_in[5];
    float* out = (float*)d_out;

    gv_kernel<<<NTILES, THREADS>>>(v4);
    dim3 grid(24, YB);   // 576 CTAs
    mlp_mma_kernel<<<grid, THREADS>>>(h4, W1, b1, W2, b2, out);
}

// round 8
// speedup vs baseline: 2.6169x; 1.0676x over previous
#include <cuda_runtime.h>
#include <cuda_fp16.h>
#include <cstdint>

#define NSAMP   131072
#define TILE    128
#define NTILES  (NSAMP / TILE)     // 1024
#define YB      24                 // 576 CTAs, 4/SM single wave
#define THREADS 128

__device__ float d_gv[6 * NSAMP];

__constant__ int c_node2gk[24] = {0,4,8,1,5,9,2,6,10,3,7,11,12,13,14,15,16,20,17,21,18,22,19,23};
__constant__ int c_node2g[24]  = {0,1,2,0,1,2,0,1,2,0,1,2,3,3,3,3,4,5,4,5,4,5,4,5};
__constant__ int c_members[24] = {0,3,6,9, 1,4,7,10, 2,5,8,11, 12,13,14,15, 16,18,20,22, 17,19,21,23};

__device__ __forceinline__ uint32_t smem_u32(const void* p) {
    uint32_t a;
    asm("{ .reg .u64 t; cvta.to.shared.u64 t, %1; cvt.u32.u64 %0, t; }" : "=r"(a) : "l"(p));
    return a;
}
__device__ __forceinline__ uint32_t h2u(__half2 h) {
    uint32_t u; __builtin_memcpy(&u, &h, 4); return u;
}

#define LDMX4(r0, r1, r2, r3, addr)                                           \
    asm volatile("ldmatrix.sync.aligned.m8n8.x4.shared.b16 {%0,%1,%2,%3}, [%4];" \
        : "=r"(r0), "=r"(r1), "=r"(r2), "=r"(r3) : "r"(addr))

#define MMA_F16(d, a0, a1, a2, a3, b0, b1)                                    \
    asm volatile(                                                             \
        "mma.sync.aligned.m16n8k16.row.col.f32.f16.f16.f32 "                  \
        "{%0,%1,%2,%3}, {%4,%5,%6,%7}, {%8,%9}, {%0,%1,%2,%3};"               \
        : "+f"(d[0]), "+f"(d[1]), "+f"(d[2]), "+f"(d[3])                      \
        : "r"(a0), "r"(a1), "r"(a2), "r"(a3), "r"(b0), "r"(b1))

// ---------------- gv pre-kernel ----------------
__global__ void gv_kernel(const int4* __restrict__ v4) {
    __shared__ int sval[TILE * 24];
    const int tid = threadIdx.x;
    const int s0  = blockIdx.x * TILE;
    #pragma unroll
    for (int i = 0; i < 6; i++)
        ((int4*)sval)[i * THREADS + tid] = v4[(size_t)s0 * 6 + i * THREADS + tid];
    __syncthreads();
    const int* vr = sval + tid * 24;
    #pragma unroll
    for (int g = 0; g < 6; g++) {
        int a = vr[c_members[g*4+0]] + vr[c_members[g*4+1]]
              + vr[c_members[g*4+2]] + vr[c_members[g*4+3]];
        d_gv[g * NSAMP + s0 + tid] = (a > 0) ? 1.f : 0.f;
    }
}

// ---------------- main kernel ----------------
__global__ __launch_bounds__(THREADS, 4)
void mlp_mma_kernel(const float4* __restrict__ h4,
                    const float*  __restrict__ W1,
                    const float*  __restrict__ b1,
                    const float*  __restrict__ W2,
                    const float*  __restrict__ b2,
                    float* __restrict__ out)
{
    // X tiles as fp16: 128 rows x 32 halves (64B rows). Warp w owns rows
    // [w*32, w*32+32) — staging AND ldmatrix consumption are warp-private.
    __shared__ __align__(128) char xhi[TILE * 64];
    __shared__ __align__(128) char xlo[TILE * 64];
    __shared__ float sB1[32], sW2[32], sB2;

    const int tid  = threadIdx.x;
    const int lane = tid & 31;
    const int w    = tid >> 5;
    const int t    = lane & 3;
    const int g    = lane >> 2;
    const int node = blockIdx.x;
    const int gk   = c_node2gk[node];
    const int grp  = c_node2g[node];

    // ---- B fragments (fp16 hi/lo), resident in regs ----
    uint32_t bhi[2][4][2], blo[2][4][2];
    {
        const float* wp = W1 + (size_t)gk * 1024;
        #pragma unroll
        for (int kf = 0; kf < 2; kf++)
            #pragma unroll
            for (int nf = 0; nf < 4; nf++) {
                int col = nf * 8 + g;
                #pragma unroll
                for (int r = 0; r < 2; r++) {
                    float w0 = wp[(kf*16 + 2*t + 8*r    ) * 32 + col];
                    float w1 = wp[(kf*16 + 2*t + 8*r + 1) * 32 + col];
                    __half2 hh = __floats2half2_rn(w0, w1);
                    float r0 = w0 - __low2float(hh);
                    float r1 = w1 - __high2float(hh);
                    bhi[kf][nf][r] = h2u(hh);
                    blo[kf][nf][r] = h2u(__floats2half2_rn(r0, r1));
                }
            }
        if (tid < 32) {
            sB1[tid] = b1[gk * 32 + tid];
            sW2[tid] = W2[gk * 32 + tid];
        }
        if (tid == 0) sB2 = b2[gk];
    }

    const uint32_t xhib = smem_u32(xhi);
    const uint32_t xlob = smem_u32(xlo);

    // ---- ldmatrix addresses (warp-private rows) ----
    uint32_t lmoff[2][2];
    {
        int rl = lane & 15, hi16 = (lane >> 4) & 1;
        #pragma unroll
        for (int mf = 0; mf < 2; mf++)
            #pragma unroll
            for (int kf = 0; kf < 2; kf++) {
                int r = w * 32 + mf * 16 + rl;
                int cs = (2 * kf + hi16) ^ ((r >> 1) & 3);
                lmoff[mf][kf] = (uint32_t)(r * 64 + cs * 16);
            }
    }
    // ---- warp-local staging map: idx = i*32 + lane -> row_l = idx>>3, c = idx&7 ----
    uint32_t stoff[8];
    int ld_row[8], ld_c[8];
    #pragma unroll
    for (int i = 0; i < 8; i++) {
        int idx = i * 32 + lane;
        int rl = idx >> 3, c = idx & 7;
        int row = w * 32 + rl;
        ld_row[i] = row; ld_c[i] = c;
        stoff[i] = (uint32_t)(row * 64 + (((c >> 1) ^ ((row >> 1) & 3)) << 4) + ((c & 1) << 3));
    }

    __syncthreads();   // sB1/sW2/sB2 ready (once)

    // ---- prefetch tile 0 (warp-private rows) ----
    float4 xr[8];
    int tcur = blockIdx.y;
    {
        const float4* src = h4 + ((size_t)tcur * TILE * 24 + node) * 8;
        #pragma unroll
        for (int i = 0; i < 8; i++)
            xr[i] = src[(size_t)ld_row[i] * 192 + ld_c[i]];
    }

    while (tcur < NTILES) {
        // ---- stage: relu + fp16 split + swizzled STS (warp-private) ----
        #pragma unroll
        for (int i = 0; i < 8; i++) {
            float4 v = xr[i];
            v.x = fmaxf(v.x, 0.f); v.y = fmaxf(v.y, 0.f);
            v.z = fmaxf(v.z, 0.f); v.w = fmaxf(v.w, 0.f);
            __half2 h01 = __floats2half2_rn(v.x, v.y);
            __half2 h23 = __floats2half2_rn(v.z, v.w);
            float l0 = v.x - __low2float(h01), l1 = v.y - __high2float(h01);
            float l2 = v.z - __low2float(h23), l3 = v.w - __high2float(h23);
            uint2 hv = make_uint2(h2u(h01), h2u(h23));
            uint2 lv = make_uint2(h2u(__floats2half2_rn(l0, l1)),
                                  h2u(__floats2half2_rn(l2, l3)));
            *(uint2*)(xhi + stoff[i]) = hv;
            *(uint2*)(xlo + stoff[i]) = lv;
        }
        __syncwarp();

        const int tnext = tcur + YB;
        // prefetch next tile (overlaps MMAs; warp-private)
        if (tnext < NTILES) {
            const float4* src = h4 + ((size_t)tnext * TILE * 24 + node) * 8;
            #pragma unroll
            for (int i = 0; i < 8; i++)
                xr[i] = src[(size_t)ld_row[i] * 192 + ld_c[i]];
        }

        // ---- mainloop ----
        float dd[2][4][4];
        #pragma unroll
        for (int mf = 0; mf < 2; mf++)
            #pragma unroll
            for (int nf = 0; nf < 4; nf++)
                #pragma unroll
                for (int i = 0; i < 4; i++) dd[mf][nf][i] = 0.f;

        #pragma unroll
        for (int kf = 0; kf < 2; kf++) {
            uint32_t ah[2][4], al[2][4];
            #pragma unroll
            for (int mf = 0; mf < 2; mf++) {
                LDMX4(ah[mf][0], ah[mf][1], ah[mf][2], ah[mf][3], xhib + lmoff[mf][kf]);
                LDMX4(al[mf][0], al[mf][1], al[mf][2], al[mf][3], xlob + lmoff[mf][kf]);
            }
            #pragma unroll
            for (int nf = 0; nf < 4; nf++)
                #pragma unroll
                for (int mf = 0; mf < 2; mf++) {
                    MMA_F16(dd[mf][nf], ah[mf][0], ah[mf][1], ah[mf][2], ah[mf][3],
                            bhi[kf][nf][0], bhi[kf][nf][1]);
                    MMA_F16(dd[mf][nf], ah[mf][0], ah[mf][1], ah[mf][2], ah[mf][3],
                            blo[kf][nf][0], blo[kf][nf][1]);
                    MMA_F16(dd[mf][nf], al[mf][0], al[mf][1], al[mf][2], al[mf][3],
                            bhi[kf][nf][0], bhi[kf][nf][1]);
                }
        }

        // ---- epilogue: +b1, relu, dot W2, quad reduce, mask, store ----
        const int s0 = tcur * TILE;
        const float bias2 = sB2;
        #pragma unroll
        for (int mf = 0; mf < 2; mf++) {
            float p0 = 0.f, p1 = 0.f;
            #pragma unroll
            for (int nf = 0; nf < 4; nf++) {
                int col = nf * 8 + 2 * t;
                float bA = sB1[col], bB = sB1[col + 1];
                float wA = sW2[col], wB = sW2[col + 1];
                p0 = fmaf(fmaxf(dd[mf][nf][0] + bA, 0.f), wA, p0);
                p0 = fmaf(fmaxf(dd[mf][nf][1] + bB, 0.f), wB, p0);
                p1 = fmaf(fmaxf(dd[mf][nf][2] + bA, 0.f), wA, p1);
                p1 = fmaf(fmaxf(dd[mf][nf][3] + bB, 0.f), wB, p1);
            }
            p0 += __shfl_xor_sync(0xFFFFFFFF, p0, 1);
            p0 += __shfl_xor_sync(0xFFFFFFFF, p0, 2);
            p1 += __shfl_xor_sync(0xFFFFFFFF, p1, 1);
            p1 += __shfl_xor_sync(0xFFFFFFFF, p1, 2);
            if (t == 0) {
                int sA = s0 + w * 32 + mf * 16 + g;
                int sB = sA + 8;
                float gA = d_gv[grp * NSAMP + sA];
                float gB = d_gv[grp * NSAMP + sB];
                out[(size_t)sA * 24 + node] = (p0 + bias2) * gA;
                out[(size_t)sB * 24 + node] = (p1 + bias2) * gB;
            }
        }
        __syncwarp();   // warp-private buffers reusable
        tcur = tnext;
    }
}

extern "C" void kernel_launch(void* const* d_in, const int* in_sizes, int n_in,
                              void* d_out, int out_size) {
    const float4* h4 = (const float4*)d_in[0];
    const int4*   v4 = (const int4*)  d_in[1];
    const float*  W1 = (const float*) d_in[2];
    const float*  b1 = (const float*) d_in[3];
    const float*  W2 = (const float*) d_in[4];
    const float*  b2 = (const float*) d_in[5];
    float* out = (float*)d_out;

    gv_kernel<<<NTILES, THREADS>>>(v4);
    dim3 grid(24, YB);   // 576 CTAs
    mlp_mma_kernel<<<grid, THREADS>>>(h4, W1, b1, W2, b2, out);
}

// round 9
// speedup vs baseline: 2.7924x; 1.0671x over previous
#include <cuda_runtime.h>
#include <cuda_fp16.h>
#include <cstdint>

#define NSAMP   131072
#define TILE    128
#define NTILES  (NSAMP / TILE)     // 1024
#define YB      24                 // 576 CTAs, 4/SM single wave
#define THREADS 128

// dynamic smem layout (bytes)
#define OFF_RAW 0                  // 2 bufs x 16KB (buf p: p*16384 + w*4096 + idx*16)
#define OFF_XHI 32768              // 8192
#define OFF_XLO 40960              // 8192
#define OFF_CB  49152              // sB1[32], sW2[32], sB2
#define DSMEM   49456

__device__ float d_gv[6 * NSAMP];

__constant__ int c_node2gk[24] = {0,4,8,1,5,9,2,6,10,3,7,11,12,13,14,15,16,20,17,21,18,22,19,23};
__constant__ int c_node2g[24]  = {0,1,2,0,1,2,0,1,2,0,1,2,3,3,3,3,4,5,4,5,4,5,4,5};
__constant__ int c_members[24] = {0,3,6,9, 1,4,7,10, 2,5,8,11, 12,13,14,15, 16,18,20,22, 17,19,21,23};

__device__ __forceinline__ uint32_t smem_u32(const void* p) {
    uint32_t a;
    asm("{ .reg .u64 t; cvta.to.shared.u64 t, %1; cvt.u32.u64 %0, t; }" : "=r"(a) : "l"(p));
    return a;
}
__device__ __forceinline__ uint32_t h2u(__half2 h) {
    uint32_t u; __builtin_memcpy(&u, &h, 4); return u;
}

#define CP16(dst, src) \
    asm volatile("cp.async.cg.shared.global [%0], [%1], 16;" :: "r"(dst), "l"(src) : "memory")
#define CP_COMMIT()  asm volatile("cp.async.commit_group;" ::: "memory")
#define CP_WAIT1()   asm volatile("cp.async.wait_group 1;" ::: "memory")

#define LDMX4(r0, r1, r2, r3, addr)                                           \
    asm volatile("ldmatrix.sync.aligned.m8n8.x4.shared.b16 {%0,%1,%2,%3}, [%4];" \
        : "=r"(r0), "=r"(r1), "=r"(r2), "=r"(r3) : "r"(addr))

#define MMA_F16(d, a0, a1, a2, a3, b0, b1)                                    \
    asm volatile(                                                             \
        "mma.sync.aligned.m16n8k16.row.col.f32.f16.f16.f32 "                  \
        "{%0,%1,%2,%3}, {%4,%5,%6,%7}, {%8,%9}, {%0,%1,%2,%3};"               \
        : "+f"(d[0]), "+f"(d[1]), "+f"(d[2]), "+f"(d[3])                      \
        : "r"(a0), "r"(a1), "r"(a2), "r"(a3), "r"(b0), "r"(b1))

// ---------------- gv pre-kernel ----------------
__global__ void gv_kernel(const int4* __restrict__ v4) {
    __shared__ int sval[256 * 24];
    const int tid = threadIdx.x;
    const int s0  = blockIdx.x * 256;
    #pragma unroll
    for (int i = 0; i < 6; i++)
        ((int4*)sval)[i * 256 + tid] = v4[(size_t)s0 * 6 + i * 256 + tid];
    __syncthreads();
    const int* vr = sval + tid * 24;
    #pragma unroll
    for (int g = 0; g < 6; g++) {
        int a = vr[c_members[g*4+0]] + vr[c_members[g*4+1]]
              + vr[c_members[g*4+2]] + vr[c_members[g*4+3]];
        d_gv[g * NSAMP + s0 + tid] = (a > 0) ? 1.f : 0.f;
    }
}

// ---------------- main kernel ----------------
__global__ __launch_bounds__(THREADS, 4)
void mlp_mma_kernel(const float4* __restrict__ h4,
                    const float*  __restrict__ W1,
                    const float*  __restrict__ b1,
                    const float*  __restrict__ W2,
                    const float*  __restrict__ b2,
                    float* __restrict__ out)
{
    extern __shared__ __align__(128) char dsm[];
    float* sB1 = (float*)(dsm + OFF_CB);
    float* sW2 = sB1 + 32;
    float* sB2 = sW2 + 32;

    const int tid  = threadIdx.x;
    const int lane = tid & 31;
    const int w    = tid >> 5;
    const int t    = lane & 3;
    const int g    = lane >> 2;
    const int node = blockIdx.x;
    const int gk   = c_node2gk[node];
    const int grp  = c_node2g[node];

    // ---- B fragments (fp16 hi/lo), resident in regs ----
    uint32_t bhi[2][4][2], blo[2][4][2];
    {
        const float* wp = W1 + (size_t)gk * 1024;
        #pragma unroll
        for (int kf = 0; kf < 2; kf++)
            #pragma unroll
            for (int nf = 0; nf < 4; nf++) {
                int col = nf * 8 + g;
                #pragma unroll
                for (int r = 0; r < 2; r++) {
                    float w0 = wp[(kf*16 + 2*t + 8*r    ) * 32 + col];
                    float w1 = wp[(kf*16 + 2*t + 8*r + 1) * 32 + col];
                    __half2 hh = __floats2half2_rn(w0, w1);
                    float r0 = w0 - __low2float(hh);
                    float r1 = w1 - __high2float(hh);
                    bhi[kf][nf][r] = h2u(hh);
                    blo[kf][nf][r] = h2u(__floats2half2_rn(r0, r1));
                }
            }
        if (tid < 32) {
            sB1[tid] = b1[gk * 32 + tid];
            sW2[tid] = W2[gk * 32 + tid];
        }
        if (tid == 0) sB2[0] = b2[gk];
    }

    const uint32_t smb  = smem_u32(dsm);
    const uint32_t xhib = smb + OFF_XHI;
    const uint32_t xlob = smb + OFF_XLO;
    const uint32_t rawb = smb + OFF_RAW + w * 4096;   // + p*16384 + idx*16

    // ---- ldmatrix addresses (warp-private rows) ----
    uint32_t lmoff[2][2];
    {
        int rl = lane & 15, hi16 = (lane >> 4) & 1;
        #pragma unroll
        for (int mf = 0; mf < 2; mf++)
            #pragma unroll
            for (int kf = 0; kf < 2; kf++) {
                int r = w * 32 + mf * 16 + rl;
                int cs = (2 * kf + hi16) ^ ((r >> 1) & 3);
                lmoff[mf][kf] = (uint32_t)(r * 64 + cs * 16);
            }
    }
    // ---- staging maps: chunk idx = i*32+lane -> (row, c) ----
    uint32_t stoff[8];          // fp16 STS offsets (swizzled)
    size_t   goff[8];           // gmem float4 offsets within a tile
    #pragma unroll
    for (int i = 0; i < 8; i++) {
        int idx = i * 32 + lane;
        int rl = idx >> 3, c = idx & 7;
        int row = w * 32 + rl;
        goff[i]  = (size_t)row * 192 + c;
        stoff[i] = (uint32_t)(row * 64 + (((c >> 1) ^ ((row >> 1) & 3)) << 4) + ((c & 1) << 3));
    }

    __syncthreads();   // sB1/sW2/sB2 ready

    // ---- prologue: depth-2 cp.async (always-commit discipline) ----
    int tcur = blockIdx.y;
    {
        const float4* src = h4 + ((size_t)tcur * TILE * 24 + node) * 8;
        #pragma unroll
        for (int i = 0; i < 8; i++)
            CP16(rawb + (uint32_t)((i * 32 + lane) * 16), src + goff[i]);
        CP_COMMIT();
        if (tcur + YB < NTILES) {
            const float4* s2 = h4 + ((size_t)(tcur + YB) * TILE * 24 + node) * 8;
            #pragma unroll
            for (int i = 0; i < 8; i++)
                CP16(rawb + 16384u + (uint32_t)((i * 32 + lane) * 16), s2 + goff[i]);
        }
        CP_COMMIT();
    }

    int p = 0;
    const float bias2 = sB2[0];
    while (tcur < NTILES) {
        CP_WAIT1();              // tile tcur resident in buffer p

        const int s0 = tcur * TILE;

        // ---- gv prefetch (early, hides L2 latency) ----
        float gA0 = 0.f, gB0 = 0.f, gA1 = 0.f, gB1 = 0.f;
        if (t == 0) {
            const float* gp = d_gv + grp * NSAMP + s0 + w * 32 + g;
            gA0 = gp[0]; gB0 = gp[8]; gA1 = gp[16]; gB1 = gp[24];
        }

        // ---- convert: LDS.128 raw -> relu + fp16 split -> swizzled STS ----
        const uint32_t rb = rawb + (uint32_t)(p * 16384);
        #pragma unroll
        for (int i = 0; i < 8; i++) {
            float4 v = *(const float4*)(dsm + (rb - smb) + (i * 32 + lane) * 16);
            v.x = fmaxf(v.x, 0.f); v.y = fmaxf(v.y, 0.f);
            v.z = fmaxf(v.z, 0.f); v.w = fmaxf(v.w, 0.f);
            __half2 h01 = __floats2half2_rn(v.x, v.y);
            __half2 h23 = __floats2half2_rn(v.z, v.w);
            float l0 = v.x - __low2float(h01), l1 = v.y - __high2float(h01);
            float l2 = v.z - __low2float(h23), l3 = v.w - __high2float(h23);
            uint2 hv = make_uint2(h2u(h01), h2u(h23));
            uint2 lv = make_uint2(h2u(__floats2half2_rn(l0, l1)),
                                  h2u(__floats2half2_rn(l2, l3)));
            *(uint2*)(dsm + OFF_XHI + stoff[i]) = hv;
            *(uint2*)(dsm + OFF_XLO + stoff[i]) = lv;
        }
        __syncwarp();

        // ---- refill buffer p with tile tcur+2*YB (raw consumed) ----
        {
            int t2 = tcur + 2 * YB;
            if (t2 < NTILES) {
                const float4* s2 = h4 + ((size_t)t2 * TILE * 24 + node) * 8;
                #pragma unroll
                for (int i = 0; i < 8; i++)
                    CP16(rb + (uint32_t)((i * 32 + lane) * 16), s2 + goff[i]);
            }
            CP_COMMIT();         // always commit (possibly empty group)
        }

        // ---- mainloop ----
        float dd[2][4][4];
        #pragma unroll
        for (int mf = 0; mf < 2; mf++)
            #pragma unroll
            for (int nf = 0; nf < 4; nf++)
                #pragma unroll
                for (int i = 0; i < 4; i++) dd[mf][nf][i] = 0.f;

        #pragma unroll
        for (int kf = 0; kf < 2; kf++) {
            uint32_t ah[2][4], al[2][4];
            #pragma unroll
            for (int mf = 0; mf < 2; mf++) {
                LDMX4(ah[mf][0], ah[mf][1], ah[mf][2], ah[mf][3], xhib + lmoff[mf][kf]);
                LDMX4(al[mf][0], al[mf][1], al[mf][2], al[mf][3], xlob + lmoff[mf][kf]);
            }
            #pragma unroll
            for (int nf = 0; nf < 4; nf++)
                #pragma unroll
                for (int mf = 0; mf < 2; mf++) {
                    MMA_F16(dd[mf][nf], ah[mf][0], ah[mf][1], ah[mf][2], ah[mf][3],
                            bhi[kf][nf][0], bhi[kf][nf][1]);
                    MMA_F16(dd[mf][nf], ah[mf][0], ah[mf][1], ah[mf][2], ah[mf][3],
                            blo[kf][nf][0], blo[kf][nf][1]);
                    MMA_F16(dd[mf][nf], al[mf][0], al[mf][1], al[mf][2], al[mf][3],
                            bhi[kf][nf][0], bhi[kf][nf][1]);
                }
        }

        // ---- epilogue: +b1, relu, dot W2, quad reduce, mask, store ----
        #pragma unroll
        for (int mf = 0; mf < 2; mf++) {
            float p0 = 0.f, p1 = 0.f;
            #pragma unroll
            for (int nf = 0; nf < 4; nf++) {
                int col = nf * 8 + 2 * t;
                float bA = sB1[col], bB = sB1[col + 1];
                float wA = sW2[col], wB = sW2[col + 1];
                p0 = fmaf(fmaxf(dd[mf][nf][0] + bA, 0.f), wA, p0);
                p0 = fmaf(fmaxf(dd[mf][nf][1] + bB, 0.f), wB, p0);
                p1 = fmaf(fmaxf(dd[mf][nf][2] + bA, 0.f), wA, p1);
                p1 = fmaf(fmaxf(dd[mf][nf][3] + bB, 0.f), wB, p1);
            }
            p0 += __shfl_xor_sync(0xFFFFFFFF, p0, 1);
            p0 += __shfl_xor_sync(0xFFFFFFFF, p0, 2);
            p1 += __shfl_xor_sync(0xFFFFFFFF, p1, 1);
            p1 += __shfl_xor_sync(0xFFFFFFFF, p1, 2);
            if (t == 0) {
                int sA = s0 + w * 32 + mf * 16 + g;
                float gA = mf ? gA1 : gA0;
                float gB = mf ? gB1 : gB0;
                out[(size_t)sA * 24 + node]       = (p0 + bias2) * gA;
                out[(size_t)(sA + 8) * 24 + node] = (p1 + bias2) * gB;
            }
        }
        __syncwarp();   // xhi/xlo reusable next tile
        p ^= 1;
        tcur += YB;
    }
}

extern "C" void kernel_launch(void* const* d_in, const int* in_sizes, int n_in,
                              void* d_out, int out_size) {
    const float4* h4 = (const float4*)d_in[0];
    const int4*   v4 = (const int4*)  d_in[1];
    const float*  W1 = (const float*) d_in[2];
    const float*  b1 = (const float*) d_in[3];
    const float*  W2 = (const float*) d_in[4];
    const float*  b2 = (const float*) d_in[5];
    float* out = (float*)d_out;

    gv_kernel<<<NSAMP / 256, 256>>>(v4);

    cudaFuncSetAttribute(mlp_mma_kernel,
                         cudaFuncAttributeMaxDynamicSharedMemorySize, DSMEM);
    dim3 grid(24, YB);   // 576 CTAs
    mlp_mma_kernel<<<grid, THREADS, DSMEM>>>(h4, W1, b1, W2, b2, out);
}